// round 10
// baseline (speedup 1.0000x reference)
#include <cuda_runtime.h>
#include <mma.h>
#include <cstdint>
using namespace nvcuda;

#define S_ 4
#define N_ 32768
#define K_ 256
#define H_ 100
#define NB 256
#define NBW 2048
#define NT 256
#define SA 120
#define SB 136
#define KP 104

#define OFF_HS 0
#define OFF_B0 61440
#define BSZ    56576
#define OFF_B1 (OFF_B0+BSZ)
#define OFF_SC (OFF_B1+BSZ)
#define OFF_US (OFF_SC+16384)
#define OFF_B2 (OFF_US+1024)
#define OFF_B3 (OFF_B2+448)
#define SMEM_TOTAL (OFF_B3+2048)

__device__ float g_part[(size_t)S_*5*NBW*K_];
__device__ float g_w[S_*K_*2];

static __device__ __forceinline__ unsigned smem_u32(const void* p){
    return (unsigned)__cvta_generic_to_shared(p);
}
static __device__ __forceinline__ void cpa16(unsigned dst, const float* src){
    asm volatile("cp.async.cg.shared.global [%0], [%1], 16;\n" :: "r"(dst), "l"(src));
}
#define CPA_COMMIT() asm volatile("cp.async.commit_group;\n" ::: "memory")
#define CPA_WAIT1()  asm volatile("cp.async.wait_group 1;\n" ::: "memory")
#define CPA_WAIT0()  asm volatile("cp.async.wait_group 0;\n" ::: "memory")

typedef wmma::fragment<wmma::matrix_a,16,16,8,wmma::precision::tf32,wmma::row_major> FragA;
typedef wmma::fragment<wmma::matrix_b,16,16,8,wmma::precision::tf32,wmma::row_major> FragB;
typedef wmma::fragment<wmma::accumulator,16,16,8,float> FragC;

// load B tile from raw fp32 smem, split hi/lo, 2 MMAs
static __device__ __forceinline__ void mma_split(FragC& fc, const FragA& fa,
                                                 const float* bp, int ldm){
    FragB fbh, fbl;
    wmma::load_matrix_sync(fbh, bp, ldm);
    #pragma unroll
    for(int i=0;i<fbh.num_elements;++i){
        float v = fbh.x[i];
        fbh.x[i] = wmma::__float_to_tf32(v);
        fbl.x[i] = wmma::__float_to_tf32(v - fbh.x[i]);
    }
    wmma::mma_sync(fc, fa, fbh, fc);
    wmma::mma_sync(fc, fa, fbl, fc);
}

// stage W3 chunk c: LP cols c*64..+63 -> B cols 0..63, MU (256+c*64..) -> cols 64..127
static __device__ __forceinline__ void stage3(float* B, const float* W3, int c, int tid){
    for(int idx=tid; idx<3200; idx+=NT){
        int r=idx>>5, t=idx&31, h=t>>4, sg=t&15;
        cpa16(smem_u32(B + r*SB + h*64 + sg*4), W3 + (size_t)r*512 + h*256 + c*64 + sg*4);
    }
}

static __device__ void gemm3_chunk(int c, const float* B, const float* hS,
    const float* uS, const float* b3S, float* sc, int s, int blk, int w, int lid)
{
    FragA fa;
    FragC fL[4], fM[4];
    #pragma unroll
    for(int t=0;t<4;++t){ wmma::fill_fragment(fL[t],0.f); wmma::fill_fragment(fM[t],0.f); }
    for(int k=0;k<13;++k){
        wmma::load_matrix_sync(fa, hS + (w*16)*SA + k*8, SA);
        #pragma unroll
        for(int t=0;t<4;++t){
            mma_split(fL[t], fa, B + k*8*SB + t*16, SB);
            mma_split(fM[t], fa, B + k*8*SB + 64 + t*16, SB);
        }
    }
    #pragma unroll
    for(int t=0;t<4;++t){
        wmma::store_matrix_sync(sc,     fL[t], 16, wmma::mem_row_major);
        wmma::store_matrix_sync(sc+256, fM[t], 16, wmma::mem_row_major);
        __syncwarp();
        int col=lid&15, rh=lid>>4;
        int kg=c*64+t*16+col;
        float bl=b3S[kg], bm=b3S[256+kg];
        float a=0,b=0,cc=0,d=0,e=0;
        #pragma unroll
        for(int r8=0;r8<8;++r8){
            int r=rh*8+r8, gr=w*16+r;
            float u0=uS[gr], u1=uS[128+gr];
            float p =__expf(sc[r*16+col]+bl);
            float pm=p*(sc[256+r*16+col]+bm);
            a+=p*u0*u0; b+=p*u0*u1; cc+=p*u1*u1; d+=pm*u0; e+=pm*u1;
        }
        a+=__shfl_xor_sync(0xffffffffu,a,16);
        b+=__shfl_xor_sync(0xffffffffu,b,16);
        cc+=__shfl_xor_sync(0xffffffffu,cc,16);
        d+=__shfl_xor_sync(0xffffffffu,d,16);
        e+=__shfl_xor_sync(0xffffffffu,e,16);
        if(lid<16){
            size_t base=(((size_t)s*5)*NBW+(size_t)(blk*8+w))*K_ + kg;
            const size_t cs=(size_t)NBW*K_;
            g_part[base]=a; g_part[base+cs]=b; g_part[base+2*cs]=cc;
            g_part[base+3*cs]=d; g_part[base+4*cs]=e;
        }
        __syncwarp();
    }
}

__global__ void __launch_bounds__(NT,1)
stageA_kernel(const float* __restrict__ U,  const float* __restrict__ W1,
              const float* __restrict__ b1, const float* __restrict__ W2,
              const float* __restrict__ b2, const float* __restrict__ W3,
              const float* __restrict__ b3)
{
    extern __shared__ char smc[];
    float* hS =(float*)(smc+OFF_HS);
    float* B0 =(float*)(smc+OFF_B0);
    float* B1 =(float*)(smc+OFF_B1);
    float* SC =(float*)(smc+OFF_SC);
    float* uS =(float*)(smc+OFF_US);
    float* b2S=(float*)(smc+OFF_B2);
    float* b3S=(float*)(smc+OFF_B3);
    const int tid=threadIdx.x, w=tid>>5, lid=tid&31;
    const int s=blockIdx.y, blk=blockIdx.x;
    float* sc = SC + w*512;

    // zero both B buffers (pad rows/cols stay zero forever)
    for(int i=tid;i<7072;i+=NT) ((float4*)B0)[i]=make_float4(0.f,0.f,0.f,0.f);
    if(tid<128){
        const float* up=U+((size_t)(s*N_+blk*128+tid)<<1);
        uS[tid]=up[0]; uS[128+tid]=up[1];
    }
    if(tid<112) b2S[tid]=(tid<H_)?b2[tid]:0.f;
    for(int i=tid;i<512;i+=NT) b3S[i]=b3[i];
    __syncthreads();

    // W2 -> B0 (rows 0..99, cols 0..99)     [group 1]
    for(int idx=tid;idx<2500;idx+=NT){
        int r=idx/25, sg=idx-r*25;
        cpa16(smem_u32(B0+r*SB+sg*4), W2+r*H_+sg*4);
    }
    CPA_COMMIT();
    stage3(B1, W3, 0, tid);  CPA_COMMIT();   // chunk0 -> B1 [group 2]

    // h1 = relu(U@W1+b1) tf32-rounded; cols 100..103 zero
    for(int idx=tid;idx<128*KP;idx+=NT){
        int m=idx/KP, i=idx-m*KP;
        float v=(i<H_)?fmaxf(fmaf(uS[m],W1[i],fmaf(uS[128+m],W1[H_+i],b1[i])),0.f):0.f;
        hS[m*SA+i]=wmma::__float_to_tf32(v);
    }
    CPA_WAIT1(); __syncthreads();            // W2 ready

    // GEMM2: 7 n-tiles, k=13x8
    {
        FragA fa; FragC fc[7];
        #pragma unroll
        for(int t=0;t<7;++t) wmma::fill_fragment(fc[t],0.f);
        for(int k=0;k<13;++k){
            wmma::load_matrix_sync(fa, hS+(w*16)*SA+k*8, SA);
            #pragma unroll
            for(int t=0;t<7;++t) mma_split(fc[t], fa, B0+k*8*SB+t*16, SB);
        }
        // h2 writeback (warp-private rows)
        #pragma unroll
        for(int t=0;t<7;++t){
            wmma::store_matrix_sync(sc, fc[t], 16, wmma::mem_row_major);
            __syncwarp();
            for(int e=lid;e<256;e+=32){
                int r=e>>4, c2=e&15, j=t*16+c2;
                hS[(w*16+r)*SA+j]=wmma::__float_to_tf32(fmaxf(sc[e]+b2S[j],0.f));
            }
            __syncwarp();
        }
    }
    __syncthreads();

    stage3(B0, W3, 1, tid); CPA_COMMIT();    // [g3]
    CPA_WAIT1(); __syncthreads();            // chunk0 ready
    gemm3_chunk(0, B1, hS, uS, b3S, sc, s, blk, w, lid);
    __syncthreads();
    stage3(B1, W3, 2, tid); CPA_COMMIT();    // [g4]
    CPA_WAIT1(); __syncthreads();            // chunk1 ready
    gemm3_chunk(1, B0, hS, uS, b3S, sc, s, blk, w, lid);
    __syncthreads();
    stage3(B0, W3, 3, tid); CPA_COMMIT();    // [g5]
    CPA_WAIT1(); __syncthreads();            // chunk2 ready
    gemm3_chunk(2, B1, hS, uS, b3S, sc, s, blk, w, lid);
    __syncthreads();
    CPA_WAIT0(); __syncthreads();            // chunk3 ready
    gemm3_chunk(3, B0, hS, uS, b3S, sc, s, blk, w, lid);
}

__global__ void __launch_bounds__(1024) stageB_kernel(const float* __restrict__ eps,
                                                      float* __restrict__ kl_out)
{
    __shared__ float sm5[5][4][K_];
    __shared__ float red[K_];
    const int s=blockIdx.x, tid=threadIdx.x, k=tid&255, q=tid>>8;
    const float* base=g_part+((size_t)s*5*NBW)*K_+k;
    const size_t cs=(size_t)NBW*K_;
    float A=0,B=0,C=0,dd=0,ee=0;
    for(int b=q*512;b<q*512+512;++b){
        size_t o=(size_t)b*K_;
        A+=base[o]; B+=base[cs+o]; C+=base[2*cs+o]; dd+=base[3*cs+o]; ee+=base[4*cs+o];
    }
    sm5[0][q][k]=A; sm5[1][q][k]=B; sm5[2][q][k]=C; sm5[3][q][k]=dd; sm5[4][q][k]=ee;
    __syncthreads();
    if(q==0){
        A =sm5[0][0][k]+sm5[0][1][k]+sm5[0][2][k]+sm5[0][3][k]+1.f;
        B =sm5[1][0][k]+sm5[1][1][k]+sm5[1][2][k]+sm5[1][3][k];
        C =sm5[2][0][k]+sm5[2][1][k]+sm5[2][2][k]+sm5[2][3][k]+1.f;
        dd=sm5[3][0][k]+sm5[3][1][k]+sm5[3][2][k]+sm5[3][3][k];
        ee=sm5[4][0][k]+sm5[4][1][k]+sm5[4][2][k]+sm5[4][3][k];
        float det=A*C-B*B, inv=1.f/det;
        float c00=C*inv, c01=-B*inv, c11=A*inv;
        float qm0=c00*dd+c01*ee, qm1=c01*dd+c11*ee;
        float l00=sqrtf(c00), l10=c01/l00, l11=sqrtf(fmaxf(c11-l10*l10,0.f));
        float e0=eps[(s*K_+k)*2], e1=eps[(s*K_+k)*2+1];
        g_w[(s*K_+k)*2]  =qm0+l00*e0;
        g_w[(s*K_+k)*2+1]=qm1+l10*e0+l11*e1;
        red[k]=0.5f*((c00+c11)+(qm0*qm0+qm1*qm1)-2.f+logf(det));
    }
    __syncthreads();
    for(int off=128;off;off>>=1){
        if(tid<off) red[tid]+=red[tid+off];
        __syncthreads();
    }
    if(tid==0) kl_out[s]=red[0];
}

__global__ void __launch_bounds__(256)
stageC_kernel(const float* __restrict__ U, float* __restrict__ out)
{
    __shared__ float w0s[K_],w1s[K_],u0s[64],u1s[64];
    const int s=blockIdx.y, n0=blockIdx.x*64, tid=threadIdx.x;
    w0s[tid]=g_w[(s*K_+tid)*2];
    w1s[tid]=g_w[(s*K_+tid)*2+1];
    if(tid<64){
        const float* up=U+((size_t)(s*N_+n0+tid)<<1);
        u0s[tid]=up[0]; u1s[tid]=up[1];
    }
    __syncthreads();
    const int kq=tid&63, r=tid>>6;
    #pragma unroll
    for(int nn=0;nn<16;++nn){
        int nl=nn*4+r;
        float u0=u0s[nl],u1=u1s[nl];
        int k=kq*4;
        float4 o;
        o.x=fmaxf(fmaf(u0,w0s[k],u1*w1s[k]),0.f);
        o.y=fmaxf(fmaf(u0,w0s[k+1],u1*w1s[k+1]),0.f);
        o.z=fmaxf(fmaf(u0,w0s[k+2],u1*w1s[k+2]),0.f);
        o.w=fmaxf(fmaf(u0,w0s[k+3],u1*w1s[k+3]),0.f);
        reinterpret_cast<float4*>(out)[(((size_t)(s*N_+n0+nl))*K_+k)>>2]=o;
    }
}

extern "C" void kernel_launch(void* const* d_in, const int* in_sizes, int n_in,
                              void* d_out, int out_size)
{
    const float* U  =(const float*)d_in[0];
    const float* eps=(const float*)d_in[1];
    const float* W1 =(const float*)d_in[2];
    const float* b1 =(const float*)d_in[3];
    const float* W2 =(const float*)d_in[4];
    const float* b2 =(const float*)d_in[5];
    const float* W3 =(const float*)d_in[6];
    const float* b3 =(const float*)d_in[7];
    float* out=(float*)d_out;

    cudaFuncSetAttribute((const void*)stageA_kernel,
                         cudaFuncAttributeMaxDynamicSharedMemorySize, SMEM_TOTAL);
    stageA_kernel<<<dim3(NB,S_),NT,SMEM_TOTAL>>>(U,W1,b1,W2,b2,W3,b3);
    stageB_kernel<<<S_,1024>>>(eps, out+(out_size-S_));
    stageC_kernel<<<dim3(N_/64,S_),256>>>(U,out);
}